// round 17
// baseline (speedup 1.0000x reference)
#include <cuda_runtime.h>
#include <cuda_bf16.h>
#include <cstdint>
#include <math.h>

#define TOT   16384
#define NPTS  4096
#define KNN   16
#define HD    128
#define IND   64
#define AP    132    // A-buffer pitch (scalar frag loads)
#define WP    136    // W-buffer pitch ([c][k'] layout; LDS.64 conflict-free)
#define WPT   72     // W-buffer pitch for K=64 weights
#define NREL  9261   // 21^3 possible rel vectors
#define NRELP 9344   // padded to 73*128
#define NROWS (TOT * KNN)   // 262144 attention rows
#define NTILE (NROWS / 128) // 2048 GEMM tiles
#define GBLK  148           // persistent gemm blocks

// ---------------- device scratch ------------------------------------------------
__device__ int   g_idx[TOT * KNN];
__device__ int   g_code[TOT * KNN];
__device__ float g_t  [TOT * HD];
__device__ float g_qg [TOT * HD];     // BN(t) @ (Wphi@Wg1) + bg1
__device__ float g_kg [TOT * HD];     // BN(t) @ (Wpsi@Wg1)
__device__ float g_v  [TOT * HD];
__device__ float g_agg[TOT * HD];
__device__ float g_h2 [NROWS * HD];   // staged tf32 relu(qg-kg+dg)
__device__ float g_part[128 * 2 * HD];
__device__ float g_stats[2 * HD];
__device__ float g_wtf[6 * HD * HD];  // tf32 [c][k']: Wg2,WqG,WkG,Walpha,Wd2,WdG
__device__ float g_wth[HD * 64];      // W_top hi, tf32 [c][k']
__device__ float g_wtl[HD * 64];      // W_top lo, tf32 [c][k']
__device__ float g_bdG[HD];           // bd2 @ Wg1
__device__ float g_dtab [NRELP * HD]; // delta(rel) table
__device__ float g_dgtab[NRELP * HD]; // delta(rel)@Wg1 table (+bdG)
__device__ unsigned int g_tick1;
__device__ unsigned int g_tick2;

__device__ __forceinline__ float to_tf32(float x) {
    unsigned int r;
    asm("cvt.rna.tf32.f32 %0, %1;" : "=r"(r) : "f"(x));
    return __uint_as_float(r);
}
__device__ __forceinline__ int permk(int k) {
    return (k & ~7) | ((k & 3) << 1) | ((k >> 2) & 1);
}

__device__ __forceinline__ void cp16(void* dst_smem, const void* src) {
    unsigned int d = (unsigned int)__cvta_generic_to_shared(dst_smem);
    asm volatile("cp.async.cg.shared.global [%0], [%1], 16;\n" :: "r"(d), "l"(src));
}
__device__ __forceinline__ void cp_commit() {
    asm volatile("cp.async.commit_group;\n");
}
template <int N>
__device__ __forceinline__ void cp_wait() {
    asm volatile("cp.async.wait_group %0;\n" :: "n"(N));
}

// ============ prep: composites + tf32 conversions (one launch) ===================
__global__ __launch_bounds__(256) void prep_kernel(const float* __restrict__ Wphi,
                                                   const float* __restrict__ Wpsi,
                                                   const float* __restrict__ Wd2,
                                                   const float* __restrict__ Wg1,
                                                   const float* __restrict__ bd2,
                                                   const float* __restrict__ Wg2,
                                                   const float* __restrict__ Walpha,
                                                   const float* __restrict__ Wtop) {
    int m = blockIdx.x;
    int tid = threadIdx.x;
    if (m >= 52) {
        int e = (m - 52) * 256 + tid;          // 0..2047
        int k = e >> 5, c = (e & 31) * 4;
        float4 v = *(const float4*)&Wtop[k * 128 + c];
        int kp = permk(k);
        float h0 = to_tf32(v.x), h1 = to_tf32(v.y);
        float h2 = to_tf32(v.z), h3 = to_tf32(v.w);
        g_wth[(c + 0) * 64 + kp] = h0;
        g_wth[(c + 1) * 64 + kp] = h1;
        g_wth[(c + 2) * 64 + kp] = h2;
        g_wth[(c + 3) * 64 + kp] = h3;
        g_wtl[(c + 0) * 64 + kp] = to_tf32(v.x - h0);
        g_wtl[(c + 1) * 64 + kp] = to_tf32(v.y - h1);
        g_wtl[(c + 2) * 64 + kp] = to_tf32(v.z - h2);
        g_wtl[(c + 3) * 64 + kp] = to_tf32(v.w - h3);
        return;
    }
    if (m >= 4) {
        int e = (m - 4) * 256 + tid;
        const float* srcs[3] = {Wg2, Walpha, Wd2};
        const int slots[3] = {0, 3, 4};
        int mm = e / 4096;
        int idx = e & 4095;
        int k = idx >> 5, c = (idx & 31) * 4;
        float4 v = *(const float4*)&srcs[mm][k * 128 + c];
        int kp = permk(k);
        float* dst = g_wtf + slots[mm] * 16384;
        dst[(c + 0) * 128 + kp] = to_tf32(v.x);
        dst[(c + 1) * 128 + kp] = to_tf32(v.y);
        dst[(c + 2) * 128 + kp] = to_tf32(v.z);
        dst[(c + 3) * 128 + kp] = to_tf32(v.w);
        return;
    }
    if (m == 3) {
        if (tid < 128) {
            float s = 0.f;
            for (int k = 0; k < 128; k++)
                s += bd2[k] * Wg1[k * 128 + tid];
            g_bdG[tid] = s;
        }
        return;
    }
    const float* A = (m == 0) ? Wphi : (m == 1) ? Wpsi : Wd2;
    const int slot = (m == 0) ? 1 : (m == 1) ? 2 : 5;
    float* dst = g_wtf + slot * 16384;
    __shared__ float As[16][128];
    __shared__ float Bs[16][128];
    int ty = tid >> 4, tx = tid & 15;
    float acc[8][8] = {};
    for (int kt = 0; kt < 128; kt += 16) {
        for (int e = tid; e < 2048; e += 256) {
            int r = e >> 4, k = e & 15;
            As[k][r] = A[r * 128 + kt + k];
        }
        for (int e = tid; e < 2048; e += 256) {
            int k = e >> 7, c = e & 127;
            Bs[k][c] = Wg1[(kt + k) * 128 + c];
        }
        __syncthreads();
        #pragma unroll
        for (int k = 0; k < 16; k++) {
            float av[8], bv[8];
            #pragma unroll
            for (int i = 0; i < 8; i++) av[i] = As[k][ty * 8 + i];
            #pragma unroll
            for (int j = 0; j < 8; j++) bv[j] = Bs[k][tx * 8 + j];
            #pragma unroll
            for (int i = 0; i < 8; i++)
                #pragma unroll
                for (int j = 0; j < 8; j++)
                    acc[i][j] += av[i] * bv[j];
        }
        __syncthreads();
    }
    #pragma unroll
    for (int i = 0; i < 8; i++) {
        int r = ty * 8 + i;
        int rp = (r & ~7) | (((r & 3) << 1) | ((r >> 2) & 1));
        #pragma unroll
        for (int j = 0; j < 8; j++)
            dst[(tx * 8 + j) * 128 + rp] = to_tf32(acc[i][j]);
    }
}

// ============================ ball query =========================================
__global__ __launch_bounds__(128) void ball_kernel(const int* __restrict__ coords) {
    __shared__ int sP[NPTS];
    int b = (blockIdx.x * 128) / NPTS;
    int base = b * NPTS;
    for (int j = threadIdx.x; j < NPTS; j += 128) {
        int4 c = *(const int4*)&coords[(size_t)(base + j) * 4];
        sP[j] = c.y | (c.z << 8) | (c.w << 16);
    }
    __syncthreads();
    int qi = blockIdx.x * 128 + threadIdx.x;
    int me = sP[qi - base];
    int qx = me & 255, qy = (me >> 8) & 255, qz = me >> 16;
    int cnt = 0, first = 0;
    int* out = g_idx + (size_t)qi * KNN;
    #pragma unroll 8
    for (int j = 0; j < NPTS; j++) {
        int p = sP[j];
        int dx = qx - (p & 255);
        int dy = qy - ((p >> 8) & 255);
        int dz = qz - (p >> 16);
        int d2 = dx * dx + dy * dy + dz * dz;
        if (d2 <= 100) {
            int gj = base + j;
            out[cnt] = gj;
            if (cnt == 0) first = gj;
            cnt++;
            if (cnt == KNN) break;
        }
    }
    for (int k = cnt; k < KNN; k++) out[k] = first;
}

// ============================ tf32 mma GEMM cores ================================
__device__ __forceinline__ void gemm_mma(const float* __restrict__ A,
                                         const float* __restrict__ W,
                                         float acc[2][4][4],
                                         int wr, int wc, int g, int t) {
    #pragma unroll
    for (int i = 0; i < 2; i++)
        #pragma unroll
        for (int j = 0; j < 4; j++)
            #pragma unroll
            for (int r = 0; r < 4; r++) acc[i][j][r] = 0.f;
    #pragma unroll 4
    for (int kk = 0; kk < 16; kk++) {
        const int k0 = kk * 8;
        unsigned int a[2][4];
        #pragma unroll
        for (int mi = 0; mi < 2; mi++) {
            const float* ap = A + (size_t)(wr * 32 + mi * 16 + g) * AP + k0 + t;
            a[mi][0] = __float_as_uint(ap[0]);
            a[mi][1] = __float_as_uint(ap[8 * AP]);
            a[mi][2] = __float_as_uint(ap[4]);
            a[mi][3] = __float_as_uint(ap[8 * AP + 4]);
        }
        #pragma unroll
        for (int ni = 0; ni < 4; ni++) {
            const float* bp = W + (size_t)(wc * 32 + ni * 8 + g) * WP + k0 + 2 * t;
            float2 bb = *(const float2*)bp;
            unsigned int b0 = __float_as_uint(bb.x);
            unsigned int b1 = __float_as_uint(bb.y);
            #pragma unroll
            for (int mi = 0; mi < 2; mi++) {
                asm volatile(
                    "mma.sync.aligned.m16n8k8.row.col.f32.tf32.tf32.f32 "
                    "{%0,%1,%2,%3}, {%4,%5,%6,%7}, {%8,%9}, {%0,%1,%2,%3};\n"
                    : "+f"(acc[mi][ni][0]), "+f"(acc[mi][ni][1]),
                      "+f"(acc[mi][ni][2]), "+f"(acc[mi][ni][3])
                    : "r"(a[mi][0]), "r"(a[mi][1]), "r"(a[mi][2]), "r"(a[mi][3]),
                      "r"(b0), "r"(b1));
            }
        }
    }
}

__device__ __forceinline__ void gemm_mma8(const float* __restrict__ A,
                                          const float* __restrict__ W,
                                          float acc[2][4][4],
                                          int wr, int wc, int g, int t) {
    #pragma unroll
    for (int kk = 0; kk < 8; kk++) {
        const int k0 = kk * 8;
        unsigned int a[2][4];
        #pragma unroll
        for (int mi = 0; mi < 2; mi++) {
            const float* ap = A + (size_t)(wr * 32 + mi * 16 + g) * AP + k0 + t;
            a[mi][0] = __float_as_uint(ap[0]);
            a[mi][1] = __float_as_uint(ap[8 * AP]);
            a[mi][2] = __float_as_uint(ap[4]);
            a[mi][3] = __float_as_uint(ap[8 * AP + 4]);
        }
        #pragma unroll
        for (int ni = 0; ni < 4; ni++) {
            const float* bp = W + (size_t)(wc * 32 + ni * 8 + g) * WPT + k0 + 2 * t;
            float2 bb = *(const float2*)bp;
            unsigned int b0 = __float_as_uint(bb.x);
            unsigned int b1 = __float_as_uint(bb.y);
            #pragma unroll
            for (int mi = 0; mi < 2; mi++) {
                asm volatile(
                    "mma.sync.aligned.m16n8k8.row.col.f32.tf32.tf32.f32 "
                    "{%0,%1,%2,%3}, {%4,%5,%6,%7}, {%8,%9}, {%0,%1,%2,%3};\n"
                    : "+f"(acc[mi][ni][0]), "+f"(acc[mi][ni][1]),
                      "+f"(acc[mi][ni][2]), "+f"(acc[mi][ni][3])
                    : "r"(a[mi][0]), "r"(a[mi][1]), "r"(a[mi][2]), "r"(a[mi][3]),
                      "r"(b0), "r"(b1));
            }
        }
    }
}

__device__ __forceinline__ void ldW_async(float* dstBase, const float* src, int tid,
                                          int nthreads) {
    for (int e = tid; e < 4096; e += nthreads) {
        int r = e >> 5, c = (e & 31) * 4;
        cp16(dstBase + r * WP + c, src + r * 128 + c);
    }
}
__device__ __forceinline__ void ldW64_async(float* dstBase, const float* src, int tid,
                                            int nthreads) {
    for (int e = tid; e < 2048; e += nthreads) {
        int r = e >> 4, c = (e & 15) * 4;
        cp16(dstBase + r * WPT + c, src + r * 64 + c);
    }
}

// ============== delta tables =====================================================
__global__ __launch_bounds__(512) void table_kernel(const float* __restrict__ Wd1,
                                                    const float* __restrict__ bd1,
                                                    const float* __restrict__ bd2) {
    extern __shared__ float sm[];
    float* BufA = sm;                    // [128][AP]
    float* W0   = BufA + 128 * AP;       // [128][WP]  Wd2
    float* W1   = W0 + 128 * WP;         // [128][WP]  WdG
    __shared__ float sWd1[384], sBd1[128];
    int tid = threadIdx.x;
    int row0 = blockIdx.x * 128;

    ldW_async(W0, g_wtf + 4 * 16384, tid, 512);  cp_commit();
    ldW_async(W1, g_wtf + 5 * 16384, tid, 512);  cp_commit();

    if (tid < 384) sWd1[tid] = Wd1[tid];
    if (tid < 128) sBd1[tid] = bd1[tid];
    __syncthreads();

    for (int e = tid; e < 128 * 128; e += 512) {
        int r = e >> 7, c = e & 127;
        int idx = row0 + r;
        if (idx > NREL - 1) idx = NREL - 1;
        float dx = (float)(idx % 21 - 10);
        float dy = (float)((idx / 21) % 21 - 10);
        float dz = (float)(idx / 441 - 10);
        float v = sBd1[c] + dx * sWd1[c] + dy * sWd1[128 + c] + dz * sWd1[256 + c];
        BufA[r * AP + c] = to_tf32(fmaxf(v, 0.f));
    }
    cp_wait<1>();
    __syncthreads();

    int wid = tid >> 5, lane = tid & 31;
    int wr = wid >> 2, wc = wid & 3;
    int g = lane >> 2, t = lane & 3;

    float acc[2][4][4];
    gemm_mma(BufA, W0, acc, wr, wc, g, t);    // delta
    #pragma unroll
    for (int mi = 0; mi < 2; mi++) {
        int r0 = row0 + wr * 32 + mi * 16 + g;
        #pragma unroll
        for (int ni = 0; ni < 4; ni++) {
            int c0 = wc * 32 + ni * 8 + 2 * t;
            float b0 = __ldg(&bd2[c0]), b1 = __ldg(&bd2[c0 + 1]);
            *(float2*)&g_dtab[(size_t)r0 * 128 + c0] =
                make_float2(acc[mi][ni][0] + b0, acc[mi][ni][1] + b1);
            *(float2*)&g_dtab[(size_t)(r0 + 8) * 128 + c0] =
                make_float2(acc[mi][ni][2] + b0, acc[mi][ni][3] + b1);
        }
    }
    cp_wait<0>();
    gemm_mma(BufA, W1, acc, wr, wc, g, t);    // delta @ Wg1 (+bdG)
    #pragma unroll
    for (int mi = 0; mi < 2; mi++) {
        int r0 = row0 + wr * 32 + mi * 16 + g;
        #pragma unroll
        for (int ni = 0; ni < 4; ni++) {
            int c0 = wc * 32 + ni * 8 + 2 * t;
            float b0 = g_bdG[c0], b1 = g_bdG[c0 + 1];
            *(float2*)&g_dgtab[(size_t)r0 * 128 + c0] =
                make_float2(acc[mi][ni][0] + b0, acc[mi][ni][1] + b1);
            *(float2*)&g_dgtab[(size_t)(r0 + 8) * 128 + c0] =
                make_float2(acc[mi][ni][2] + b0, acc[mi][ni][3] + b1);
        }
    }
}

// ================ t = x @ W_top + b_top (tf32 split, fp32-accurate) ==============
__global__ __launch_bounds__(512) void topproj_kernel(const float* __restrict__ x,
                                                      const float* __restrict__ bias) {
    extern __shared__ float sm[];
    float* BufA  = sm;                    // [128][AP]
    float* W0    = BufA + 128 * AP;       // [128][WPT]
    float* W1    = W0 + 128 * WPT;        // [128][WPT]
    float* redS  = W1 + 128 * WPT;        // [32][128]
    float* redSS = redS + 32 * 128;       // [32][128]
    __shared__ double dS[2][128], dSS[2][128];
    __shared__ bool sLast;

    int tid = threadIdx.x;
    int row0 = blockIdx.x * 128;

    ldW64_async(W0, g_wth, tid, 512);  cp_commit();
    ldW64_async(W1, g_wtl, tid, 512);  cp_commit();

    for (int e = tid; e < 2048; e += 512) {
        int r = e >> 4, s = (e & 15) * 4;
        float4 v = *(const float4*)&x[(size_t)(row0 + r) * 64 + s];
        float h0 = to_tf32(v.x), h1 = to_tf32(v.y);
        float h2 = to_tf32(v.z), h3 = to_tf32(v.w);
        float* bh = &BufA[r * AP + s];
        bh[0] = h0; bh[1] = h1; bh[2] = h2; bh[3] = h3;
        float* bl = bh + 64;
        bl[0] = to_tf32(v.x - h0); bl[1] = to_tf32(v.y - h1);
        bl[2] = to_tf32(v.z - h2); bl[3] = to_tf32(v.w - h3);
    }
    cp_wait<0>();
    __syncthreads();

    int wid = tid >> 5, lane = tid & 31;
    int wr = wid >> 2, wc = wid & 3;
    int g = lane >> 2, t = lane & 3;

    float acc[2][4][4];
    #pragma unroll
    for (int i = 0; i < 2; i++)
        #pragma unroll
        for (int j = 0; j < 4; j++)
            #pragma unroll
            for (int r = 0; r < 4; r++) acc[i][j][r] = 0.f;
    gemm_mma8(BufA, W0, acc, wr, wc, g, t);
    gemm_mma8(BufA, W1, acc, wr, wc, g, t);
    gemm_mma8(BufA + 64, W0, acc, wr, wc, g, t);

    #pragma unroll
    for (int ni = 0; ni < 4; ni++) {
        int c0 = wc * 32 + ni * 8 + 2 * t;
        float b0 = __ldg(&bias[c0]), b1 = __ldg(&bias[c0 + 1]);
        float v00 = acc[0][ni][0] + b0, v01 = acc[0][ni][1] + b1;
        float v02 = acc[0][ni][2] + b0, v03 = acc[0][ni][3] + b1;
        float v10 = acc[1][ni][0] + b0, v11 = acc[1][ni][1] + b1;
        float v12 = acc[1][ni][2] + b0, v13 = acc[1][ni][3] + b1;
        int r0 = wr * 32 + g;
        *(float2*)&g_t[(size_t)(row0 + r0) * 128 + c0]      = make_float2(v00, v01);
        *(float2*)&g_t[(size_t)(row0 + r0 + 8) * 128 + c0]  = make_float2(v02, v03);
        *(float2*)&g_t[(size_t)(row0 + r0 + 16) * 128 + c0] = make_float2(v10, v11);
        *(float2*)&g_t[(size_t)(row0 + r0 + 24) * 128 + c0] = make_float2(v12, v13);
        int rr = wr * 8 + g;
        redS[rr * 128 + c0]      = v00 + v02 + v10 + v12;
        redS[rr * 128 + c0 + 1]  = v01 + v03 + v11 + v13;
        redSS[rr * 128 + c0]     = v00 * v00 + v02 * v02 + v10 * v10 + v12 * v12;
        redSS[rr * 128 + c0 + 1] = v01 * v01 + v03 * v03 + v11 * v11 + v13 * v13;
    }
    __syncthreads();
    if (tid < 128) {
        float s = 0.f, ss = 0.f;
        #pragma unroll
        for (int u = 0; u < 32; u++) { s += redS[u * 128 + tid]; ss += redSS[u * 128 + tid]; }
        g_part[blockIdx.x * 256 + tid]       = s;
        g_part[blockIdx.x * 256 + 128 + tid] = ss;
    }
    __threadfence();
    __syncthreads();
    if (tid == 0)
        sLast = (atomicAdd(&g_tick1, 1u) == gridDim.x - 1);
    __syncthreads();
    if (sLast) {
        if (tid < 256) {
            int c = tid & 127, sub = tid >> 7;
            double s = 0.0, ss = 0.0;
            for (int b = sub; b < 128; b += 2) {
                s  += (double)g_part[b * 256 + c];
                ss += (double)g_part[b * 256 + 128 + c];
            }
            dS[sub][c] = s; dSS[sub][c] = ss;
        }
        __syncthreads();
        if (tid < 128) {
            double S = dS[0][tid] + dS[1][tid];
            double SS = dSS[0][tid] + dSS[1][tid];
            double m = S / (double)TOT;
            double var = SS / (double)TOT - m * m;
            g_stats[tid]       = (float)m;
            g_stats[128 + tid] = rsqrtf((float)var + 1e-5f);
        }
        if (tid == 0) g_tick1 = 0u;
    }
}

// ============== qg,kg,v = normalize(t) @ {WqG,WkG,Walpha}; qg += bg1 =============
__global__ __launch_bounds__(512) void qkv_kernel(const float* __restrict__ g1v,
                                                  const float* __restrict__ be1,
                                                  const float* __restrict__ bg1) {
    extern __shared__ float sm[];
    float* BufA = sm;                    // [128][AP]
    float* W0   = BufA + 128 * AP;       // [128][WP]
    float* W1   = W0 + 128 * WP;         // [128][WP]
    __shared__ float sScale[128], sShift[128];
    int tid = threadIdx.x;

    ldW_async(W0, g_wtf + 1 * 16384, tid, 512);  cp_commit();
    ldW_async(W1, g_wtf + 2 * 16384, tid, 512);  cp_commit();

    if (tid < 128) {
        float m = g_stats[tid], is = g_stats[128 + tid];
        float sc = is * g1v[tid];
        sScale[tid] = sc;
        sShift[tid] = be1[tid] - m * sc;
    }
    __syncthreads();
    int row0 = blockIdx.x * 128;
    for (int e = tid; e < 4096; e += 512) {
        int r = e >> 5, s = (e & 31) * 4;
        float4 v = *(const float4*)&g_t[(size_t)(row0 + r) * 128 + s];
        float4 o;
        o.x = to_tf32(v.x * sScale[s] + sShift[s]);
        o.y = to_tf32(v.y * sScale[s + 1] + sShift[s + 1]);
        o.z = to_tf32(v.z * sScale[s + 2] + sShift[s + 2]);
        o.w = to_tf32(v.w * sScale[s + 3] + sShift[s + 3]);
        *(float4*)&BufA[r * AP + s] = o;
    }

    int wid = tid >> 5, lane = tid & 31;
    int wr = wid >> 2, wc = wid & 3;
    int g = lane >> 2, t = lane & 3;

    #pragma unroll 1
    for (int widx = 0; widx < 3; widx++) {
        float* out = (widx == 0) ? g_qg : (widx == 1) ? g_kg : g_v;
        const float* Wb = (widx == 1) ? W1 : W0;
        if (widx < 2) { cp_wait<1>(); } else { cp_wait<0>(); }
        __syncthreads();

        float acc[2][4][4];
        gemm_mma(BufA, Wb, acc, wr, wc, g, t);
        __syncthreads();

        if (widx == 0) {
            ldW_async(W0, g_wtf + 3 * 16384, tid, 512);
            cp_commit();
        }

        #pragma unroll
        for (int mi = 0; mi < 2; mi++) {
            int r0 = row0 + wr * 32 + mi * 16 + g;
            #pragma unroll
            for (int ni = 0; ni < 4; ni++) {
                int c0 = wc * 32 + ni * 8 + 2 * t;
                float b0 = 0.f, b1 = 0.f;
                if (widx == 0) { b0 = __ldg(&bg1[c0]); b1 = __ldg(&bg1[c0 + 1]); }
                *(float2*)&out[(size_t)r0 * 128 + c0] =
                    make_float2(acc[mi][ni][0] + b0, acc[mi][ni][1] + b1);
                *(float2*)&out[(size_t)(r0 + 8) * 128 + c0] =
                    make_float2(acc[mi][ni][2] + b0, acc[mi][ni][3] + b1);
            }
        }
    }
}

// ================== attention stage: h2 rows to global ===========================
// row r: i = r/16; j = g_idx[r]; h2[r] = tf32(relu(qg[i] - kg[j] + dgtab[code]))
__global__ __launch_bounds__(256) void stage_kernel(const int* __restrict__ coords) {
    int tid = threadIdx.x;
    int row = blockIdx.x * 8 + (tid >> 5);
    int lane = tid & 31;
    int i = row >> 4;
    int j = g_idx[row];
    int4 ci = *(const int4*)&coords[(size_t)i * 4];
    int4 cj = *(const int4*)&coords[(size_t)j * 4];
    int code = (ci.y - cj.y + 10) + 21 * (ci.z - cj.z + 10) + 441 * (ci.w - cj.w + 10);
    if (lane == 0) g_code[row] = code;
    int s = lane * 4;
    float4 qv = *(const float4*)&g_qg[(size_t)i * 128 + s];
    float4 kg = *(const float4*)&g_kg[(size_t)j * 128 + s];
    float4 dg = *(const float4*)&g_dgtab[(size_t)code * 128 + s];
    float4 o;
    o.x = to_tf32(fmaxf(qv.x - kg.x + dg.x, 0.f));
    o.y = to_tf32(fmaxf(qv.y - kg.y + dg.y, 0.f));
    o.z = to_tf32(fmaxf(qv.z - kg.z + dg.z, 0.f));
    o.w = to_tf32(fmaxf(qv.w - kg.w + dg.w, 0.f));
    *(float4*)&g_h2[(size_t)row * 128 + s] = o;
}

// ================== attention GEMM: persistent, Wg2-resident, pipelined ==========
// logits = h2 @ Wg2 + bg2; softmax over K; agg = sum attn*(v+dtab)
__global__ __launch_bounds__(512) void attn_gemm_kernel(const float* __restrict__ bg2) {
    extern __shared__ float sm[];
    float* Wsm = sm;                       // [128][WP]  Wg2
    float* A0  = Wsm + 128 * WP;           // [128][AP]
    float* A1  = A0 + 128 * AP;            // [128][AP]
    int* sIdx0  = (int*)(A1 + 128 * AP);   // [128]
    int* sCode0 = sIdx0 + 128;
    int* sIdx1  = sCode0 + 128;
    int* sCode1 = sIdx1 + 128;

    int tid = threadIdx.x;
    int wid = tid >> 5, lane = tid & 31;
    int wr = wid >> 2, wc = wid & 3;
    int g = lane >> 2, t = lane & 3;

    ldW_async(Wsm, g_wtf, tid, 512);       // Wg2 (stays resident)

    int tile = blockIdx.x;
    // issue first A tile + metadata into buffer 0
    {
        const float* src = g_h2 + (size_t)tile * 128 * 128;
        for (int e = tid; e < 4096; e += 512) {
            int r = e >> 5, c = (e & 31) * 4;
            cp16(A0 + r * AP + c, src + r * 128 + c);
        }
        if (tid < 128) {
            sIdx0[tid]  = g_idx[tile * 128 + tid];
            sCode0[tid] = g_code[tile * 128 + tid];
        }
    }
    cp_commit();       // one group: Wg2 + A tile0

    int cur = 0;
    for (; tile < NTILE; tile += GBLK) {
        float* Acur = cur ? A1 : A0;
        float* Anxt = cur ? A0 : A1;
        int* sIdxC  = cur ? sIdx1 : sIdx0;
        int* sCodeC = cur ? sCode1 : sCode0;
        int* sIdxN  = cur ? sIdx0 : sIdx1;
        int* sCodeN = cur ? sCode0 : sCode1;

        cp_wait<0>();          // current tile resident (pending next not yet issued)
        __syncthreads();       // metadata visible; prior GEMM readers done

        int nxt = tile + GBLK;
        if (nxt < NTILE) {     // issue next tile during this tile's GEMM
            const float* src = g_h2 + (size_t)nxt * 128 * 128;
            for (int e = tid; e < 4096; e += 512) {
                int r = e >> 5, c = (e & 31) * 4;
                cp16(Anxt + r * AP + c, src + r * 128 + c);
            }
            if (tid < 128) {
                sIdxN[tid]  = g_idx[nxt * 128 + tid];
                sCodeN[tid] = g_code[nxt * 128 + tid];
            }
            cp_commit();
        }

        float acc2[2][4][4];
        gemm_mma(Acur, Wsm, acc2, wr, wc, g, t);
        __syncthreads();       // all warps finished reading Acur

        int p0 = tile * 8;
        #pragma unroll
        for (int mi = 0; mi < 2; mi++) {
            int r0 = wr * 32 + mi * 16 + g;
            int r1 = r0 + 8;
            int pl = wr * 2 + mi;
            int gi0 = sIdxC[r0], gi1 = sIdxC[r1];
            int cd0 = sCodeC[r0], cd1 = sCodeC[r1];
            #pragma unroll
            for (int ni = 0; ni < 4; ni++) {
                int c0 = wc * 32 + ni * 8 + 2 * t;
                float b0 = __ldg(&bg2[c0]), b1 = __ldg(&bg2[c0 + 1]);
                float l00 = acc2[mi][ni][0] + b0, l01 = acc2[mi][ni][1] + b1;
                float l10 = acc2[mi][ni][2] + b0, l11 = acc2[mi][ni][3] + b1;
                float2 v0 = *(const float2*)&g_v[(size_t)gi0 * 128 + c0];
                float2 v1 = *(const float2*)&g_v[(size_t)gi1 * 128 + c0];
                float2 d0 = *(const float2*)&g_dtab[(size_t)cd0 * 128 + c0];
                float2 d1 = *(const float2*)&g_dtab[(size_t)cd1 * 128 + c0];
                float w00 = v0.x + d0.x, w01 = v0.y + d0.y;
                float w10 = v1.x + d1.x, w11 = v1.y + d1.y;

                float m0 = fmaxf(l00, l10);
                m0 = fmaxf(m0, __shfl_xor_sync(0xffffffffu, m0, 4));
                m0 = fmaxf(m0, __shfl_xor_sync(0xffffffffu, m0, 8));
                m0 = fmaxf(m0, __shfl_xor_sync(0xffffffffu, m0, 16));
                float m1 = fmaxf(l01, l11);
                m1 = fmaxf(m1, __shfl_xor_sync(0xffffffffu, m1, 4));
                m1 = fmaxf(m1, __shfl_xor_sync(0xffffffffu, m1, 8));
                m1 = fmaxf(m1, __shfl_xor_sync(0xffffffffu, m1, 16));

                float e00 = __expf(l00 - m0), e10 = __expf(l10 - m0);
                float e01 = __expf(l01 - m1), e11 = __expf(l11 - m1);
                float s0 = e00 + e10, s1 = e01 + e11;
                float a0 = e00 * w00 + e10 * w10;
                float a1 = e01 * w01 + e11 * w11;
                s0 += __shfl_xor_sync(0xffffffffu, s0, 4);
                s0 += __shfl_xor_sync(0xffffffffu, s0, 8);
                s0 += __shfl_xor_sync(0xffffffffu, s0, 16);
                s1 += __shfl_xor_sync(0xffffffffu, s1, 4);
                s1 += __shfl_xor_sync(0xffffffffu, s1, 8);
                s1 += __shfl_xor_sync(0xffffffffu, s1, 16);
                a0 += __shfl_xor_sync(0xffffffffu, a0, 4);
                a0 += __shfl_xor_sync(0xffffffffu, a0, 8);
                a0 += __shfl_xor_sync(0xffffffffu, a0, 16);
                a1 += __shfl_xor_sync(0xffffffffu, a1, 4);
                a1 += __shfl_xor_sync(0xffffffffu, a1, 8);
                a1 += __shfl_xor_sync(0xffffffffu, a1, 16);

                if (g == 0)
                    *(float2*)&g_agg[(size_t)(p0 + pl) * 128 + c0] =
                        make_float2(a0 / s0, a1 / s1);
            }
        }
        cur ^= 1;
    }
}

// ========== down-proj: out = agg @ W_down + b_down, fused BN partials ===========
__global__ __launch_bounds__(256) void down_kernel(const float* __restrict__ W,
                                                   const float* __restrict__ bias,
                                                   float* __restrict__ out) {
    __shared__ float As[16][128];
    __shared__ float Bs[16][64];
    __shared__ float redS[16][64];
    __shared__ float redSS[16][64];
    __shared__ double dS[4][64];
    __shared__ double dSS[4][64];
    __shared__ bool  sLast;
    int tid = threadIdx.x;
    int ty = tid >> 4, tx = tid & 15;
    int row0 = blockIdx.x * 128;
    float acc[8][4] = {};
    for (int kt = 0; kt < 128; kt += 16) {
        for (int e = tid; e < 512; e += 256) {
            int r = e >> 2, s = e & 3;
            float4 v = *(const float4*)&g_agg[(size_t)(row0 + r) * 128 + kt + s * 4];
            As[s * 4 + 0][r] = v.x; As[s * 4 + 1][r] = v.y;
            As[s * 4 + 2][r] = v.z; As[s * 4 + 3][r] = v.w;
        }
        if (tid < 256) {
            int k = tid >> 4, s = tid & 15;
            *(float4*)&Bs[k][s * 4] = *(const float4*)&W[(size_t)(kt + k) * 64 + s * 4];
        }
        __syncthreads();
        #pragma unroll
        for (int k = 0; k < 16; k++) {
            float4 a0 = *(const float4*)&As[k][ty * 8];
            float4 a1 = *(const float4*)&As[k][ty * 8 + 4];
            float4 b = *(const float4*)&Bs[k][tx * 4];
            float av[8] = {a0.x, a0.y, a0.z, a0.w, a1.x, a1.y, a1.z, a1.w};
            float bv[4] = {b.x, b.y, b.z, b.w};
            #pragma unroll
            for (int i = 0; i < 8; i++)
                #pragma unroll
                for (int j = 0; j < 4; j++)
                    acc[i][j] += av[i] * bv[j];
        }
        __syncthreads();
    }
    #pragma unroll
    for (int j = 0; j < 4; j++) {
        float b = __ldg(&bias[tx * 4 + j]);
        float s = 0.f, ss = 0.f;
        #pragma unroll
        for (int i = 0; i < 8; i++) {
            float v = acc[i][j] + b;
            out[(size_t)(row0 + ty * 8 + i) * 64 + tx * 4 + j] = v;
            s += v; ss += v * v;
        }
        redS[ty][tx * 4 + j] = s;
        redSS[ty][tx * 4 + j] = ss;
    }
    __syncthreads();
    if (tid < 64) {
        float s = 0.f, ss = 0.f;
        #pragma unroll
        for (int u = 0; u < 16; u++) { s += redS[u][tid]; ss += redSS[u][tid]; }
        g_part[blockIdx.x * 128 + tid]      = s;
        g_part[blockIdx.x * 128 + 64 + tid] = ss;
    }
    __threadfence();
    __syncthreads();
    if (tid == 0)
        sLast = (atomicAdd(&g_tick2, 1u) == gridDim.x - 1);
    __syncthreads();
    if (sLast) {
        int c = tid & 63, sub = tid >> 6;
        double s = 0.0, ss = 0.0;
        for (int b = sub; b < 128; b += 4) {
            s  += (double)g_part[b * 128 + c];
            ss += (double)g_part[b * 128 + 64 + c];
        }
        dS[sub][c] = s; dSS[sub][c] = ss;
        __syncthreads();
        if (tid < 64) {
            double S = dS[0][tid] + dS[1][tid] + dS[2][tid] + dS[3][tid];
            double SS = dSS[0][tid] + dSS[1][tid] + dSS[2][tid] + dSS[3][tid];
            double m = S / (double)TOT;
            double var = SS / (double)TOT - m * m;
            g_stats[tid]      = (float)m;
            g_stats[64 + tid] = rsqrtf((float)var + 1e-5f);
        }
        if (tid == 0) g_tick2 = 0u;
    }
}

// ============================ final BN + residual ================================
__global__ __launch_bounds__(256) void final_kernel(const float* __restrict__ x,
                                                    const float* __restrict__ g2,
                                                    const float* __restrict__ be2,
                                                    float* __restrict__ out) {
    int e = blockIdx.x * 256 + threadIdx.x;
    if (e < TOT * IND) {
        int c = e & 63;
        float m = g_stats[c], is = g_stats[IND + c];
        out[e] = (out[e] - m) * is * g2[c] + be2[c] + x[e];
    }
}

// ============================ launch =============================================
extern "C" void kernel_launch(void* const* d_in, const int* in_sizes, int n_in,
                              void* d_out, int out_size) {
    const int*   coords  = (const int*)  d_in[0];
    const float* x       = (const float*)d_in[1];
    const float* W_top   = (const float*)d_in[2];
    const float* b_top   = (const float*)d_in[3];
    const float* g1      = (const float*)d_in[4];
    const float* be1     = (const float*)d_in[5];
    const float* W_phi   = (const float*)d_in[6];
    const float* W_psi   = (const float*)d_in[7];
    const float* W_alpha = (const float*)d_in[8];
    const float* Wd1     = (const float*)d_in[9];
    const float* bd1     = (const float*)d_in[10];
    const float* Wd2     = (const float*)d_in[11];
    const float* bd2     = (const float*)d_in[12];
    const float* Wg1     = (const float*)d_in[13];
    const float* bg1     = (const float*)d_in[14];
    const float* Wg2     = (const float*)d_in[15];
    const float* bg2     = (const float*)d_in[16];
    const float* W_down  = (const float*)d_in[17];
    const float* b_down  = (const float*)d_in[18];
    const float* g2      = (const float*)d_in[19];
    const float* be2     = (const float*)d_in[20];
    float* out = (float*)d_out;

    const size_t SMEM_Q = (size_t)(128 * AP + 2 * 128 * WP) * 4;
    const size_t SMEM_T = (size_t)(128 * AP + 2 * 128 * WPT + 2 * 32 * 128) * 4;
    const size_t SMEM_G = (size_t)(128 * WP + 2 * 128 * AP) * 4 + 4 * 128 * 4;
    cudaFuncSetAttribute(qkv_kernel, cudaFuncAttributeMaxDynamicSharedMemorySize,
                         (int)SMEM_Q);
    cudaFuncSetAttribute(table_kernel, cudaFuncAttributeMaxDynamicSharedMemorySize,
                         (int)SMEM_Q);
    cudaFuncSetAttribute(topproj_kernel, cudaFuncAttributeMaxDynamicSharedMemorySize,
                         (int)SMEM_T);
    cudaFuncSetAttribute(attn_gemm_kernel, cudaFuncAttributeMaxDynamicSharedMemorySize,
                         (int)SMEM_G);

    prep_kernel<<<60, 256>>>(W_phi, W_psi, Wd2, Wg1, bd2, Wg2, W_alpha, W_top);
    ball_kernel<<<TOT / 128, 128>>>(coords);
    table_kernel<<<NRELP / 128, 512, SMEM_Q>>>(Wd1, bd1, bd2);
    topproj_kernel<<<TOT / 128, 512, SMEM_T>>>(x, b_top);
    qkv_kernel<<<TOT / 128, 512, SMEM_Q>>>(g1, be1, bg1);
    stage_kernel<<<NROWS / 8, 256>>>(coords);
    attn_gemm_kernel<<<GBLK, 512, SMEM_G>>>(bg2);
    down_kernel<<<TOT / 128, 256>>>(W_down, b_down, out);
    final_kernel<<<(TOT * IND + 255) / 256, 256>>>(x, g2, be2, out);
}